// round 16
// baseline (speedup 1.0000x reference)
#include <cuda_runtime.h>
#include <cuda_bf16.h>
#include <cuda_fp16.h>
#include <math.h>
#include <stdint.h>

#define N_NODES 50000
#define N_EDGES 800000
#define HID 256
#define NHEAD 8
#define HDIM 32
#define NLAYER 3
#define ATTN_SCALE 0.17677669529663687f   // 32^-0.5
#define CAP 512                            // per-node smem edge capacity

typedef __nv_bfloat16 bf16;

// ---------------- scratch (static device globals; no allocs allowed) --------
__device__ float g_h[N_NODES * HID];       // fp32 h (LN residual)
__device__ bf16  g_h_hi[N_NODES * HID];    // h split (head GEMM only)
__device__ bf16  g_h_lo[N_NODES * HID];
__device__ __half g_h_f16[N_NODES * HID];  // h fp16 (QKV + Wm GEMM A)
__device__ __half g_agg_f16[N_NODES * HID];// agg fp16 (Wo GEMM A)
__device__ __half g_ao_f16[N_NODES * HID]; // aggO fp16 (Wm GEMM A2)
__device__ float g_upd[N_NODES * HID];     // Wm output (fp32)
__device__ float g_hid[N_NODES * HID];     // head hidden (fp32, 128 used)
__device__ __half g_qh[N_NODES * HID];     // Q fp16
__device__ __half g_kh[N_NODES * HID];     // K fp16
__device__ __half g_vh[N_NODES * HID];     // V fp16
__device__ int g_src[N_EDGES];
__device__ int g_dst[N_EDGES];
__device__ int g_perm[N_EDGES];            // edges sorted by dst (CSR)
__device__ int g_rowstart[N_NODES + 1];
__device__ int g_cnt[N_NODES];
__device__ int g_cursor[N_NODES];
__device__ int g_is64;

// pre-converted weights
#define OFF_WQ 0
#define OFF_WK 196608
#define OFF_WV 393216
#define OFF_WO 589824
#define OFF_WM 983040
#define OFF_WH1 1376256
#define W_TOTAL 1409024
__device__ bf16 g_w_hi[W_TOTAL];
__device__ bf16 g_w_lo[W_TOTAL];
__device__ __half g_w_f16[W_TOTAL];        // fp16 copy (QKV/Wo/Wm regions)

__device__ __forceinline__ void split_bf16(float v, bf16& hi, bf16& lo) {
    hi = __float2bfloat16(v);
    lo = __float2bfloat16(v - __bfloat162float(hi));
}

// ---------------- index dtype detection + conversion ------------------------
__global__ void detect_idx(const int* __restrict__ raw) {
    __shared__ int any;
    if (threadIdx.x == 0) any = 0;
    __syncthreads();
    for (int i = threadIdx.x; i < 2048; i += blockDim.x)
        if (raw[2 * i + 1] != 0) any = 1;
    __syncthreads();
    if (threadIdx.x == 0) g_is64 = any ? 0 : 1;
}

__global__ void convert_idx(const int* __restrict__ raw) {
    int e = blockIdx.x * blockDim.x + threadIdx.x;
    if (e >= N_EDGES) return;
    int s, d;
    if (g_is64) {
        s = raw[2 * e];
        d = raw[2 * (N_EDGES + e)];
    } else {
        s = raw[e];
        d = raw[N_EDGES + e];
    }
    s = min(max(s, 0), N_NODES - 1);
    d = min(max(d, 0), N_NODES - 1);
    g_src[e] = s;
    g_dst[e] = d;
}

// ---------------- weight pre-conversion -------------------------------------
__global__ void convert_w(const float* __restrict__ src, int n, int off,
                          int f16) {
    int i = blockIdx.x * blockDim.x + threadIdx.x;
    if (i >= n) return;
    float v = src[i];
    bf16 hi, lo;
    split_bf16(v, hi, lo);
    g_w_hi[off + i] = hi;
    g_w_lo[off + i] = lo;
    if (f16) g_w_f16[off + i] = __float2half(v);
}

// ---------------- CSR build --------------------------------------------------
__global__ void zero_cnt() {
    int i = blockIdx.x * blockDim.x + threadIdx.x;
    if (i < N_NODES) g_cnt[i] = 0;
}

__global__ void count_deg() {
    int e = blockIdx.x * blockDim.x + threadIdx.x;
    if (e >= N_EDGES) return;
    atomicAdd(&g_cnt[g_dst[e]], 1);
}

__global__ void scan_rowstart() {     // 1 block, 1024 threads
    __shared__ int sm[1024];
    int t = threadIdx.x;
    int run = 0;
    for (int base = 0; base < N_NODES; base += 1024) {
        int idx = base + t;
        int v = (idx < N_NODES) ? g_cnt[idx] : 0;
        sm[t] = v;
        __syncthreads();
        for (int off = 1; off < 1024; off <<= 1) {
            int x = (t >= off) ? sm[t - off] : 0;
            __syncthreads();
            sm[t] += x;
            __syncthreads();
        }
        if (idx < N_NODES) g_rowstart[idx] = run + sm[t] - v;
        run += sm[1023];
        __syncthreads();
    }
    if (t == 0) g_rowstart[N_NODES] = run;
}

__global__ void copy_cursor() {
    int i = blockIdx.x * blockDim.x + threadIdx.x;
    if (i < N_NODES) g_cursor[i] = g_rowstart[i];
}

__global__ void scatter_perm() {
    int e = blockIdx.x * blockDim.x + threadIdx.x;
    if (e >= N_EDGES) return;
    int pos = atomicAdd(&g_cursor[g_dst[e]], 1);
    g_perm[pos] = e;
}

// ---------------- input projection: h = relu(x @ W_in + b_in) ---------------
__global__ void input_proj(const float* __restrict__ x,
                           const float* __restrict__ W,
                           const float* __restrict__ b) {
    int idx = blockIdx.x * blockDim.x + threadIdx.x;
    if (idx >= N_NODES * HID) return;
    int n = idx >> 8;
    int j = idx & 255;
    float acc = b[j];
#pragma unroll
    for (int f = 0; f < 10; f++) acc += x[n * 10 + f] * W[f * HID + j];
    float r = fmaxf(acc, 0.0f);
    g_h[idx] = r;
    g_h_f16[idx] = __float2half(r);
}

// ---------------- tensor-core GEMM helpers -----------------------------------
__device__ __forceinline__ void mma_bf16(float* c, const unsigned* a,
                                         const unsigned* b) {
    asm volatile(
        "mma.sync.aligned.m16n8k16.row.col.f32.bf16.bf16.f32 "
        "{%0,%1,%2,%3}, {%4,%5,%6,%7}, {%8,%9}, {%0,%1,%2,%3};\n"
        : "+f"(c[0]), "+f"(c[1]), "+f"(c[2]), "+f"(c[3])
        : "r"(a[0]), "r"(a[1]), "r"(a[2]), "r"(a[3]), "r"(b[0]), "r"(b[1]));
}
__device__ __forceinline__ void mma_f16(float* c, const unsigned* a,
                                        const unsigned* b) {
    asm volatile(
        "mma.sync.aligned.m16n8k16.row.col.f32.f16.f16.f32 "
        "{%0,%1,%2,%3}, {%4,%5,%6,%7}, {%8,%9}, {%0,%1,%2,%3};\n"
        : "+f"(c[0]), "+f"(c[1]), "+f"(c[2]), "+f"(c[3])
        : "r"(a[0]), "r"(a[1]), "r"(a[2]), "r"(a[3]), "r"(b[0]), "r"(b[1]));
}
__device__ __forceinline__ void ldsm4(unsigned* r, unsigned addr) {
    asm volatile(
        "ldmatrix.sync.aligned.m8n8.x4.shared.b16 {%0,%1,%2,%3}, [%4];\n"
        : "=r"(r[0]), "=r"(r[1]), "=r"(r[2]), "=r"(r[3]) : "r"(addr));
}
__device__ __forceinline__ void ldsm4t(unsigned* r, unsigned addr) {
    asm volatile(
        "ldmatrix.sync.aligned.m8n8.x4.trans.shared.b16 {%0,%1,%2,%3}, [%4];\n"
        : "=r"(r[0]), "=r"(r[1]), "=r"(r[2]), "=r"(r[3]) : "r"(addr));
}
__device__ __forceinline__ void cp16(uint32_t dst, const void* src, int sz) {
    asm volatile("cp.async.cg.shared.global [%0], [%1], 16, %2;"
                 :: "r"(dst), "l"(src), "r"(sz));
}

#define LDA_B 80      // A row stride bytes (40 halves)
#define LDB_B 272     // B row stride bytes (136 halves)

// ====================== fp16 single-term QKV GEMM ===========================
#define F16_BUF 18944               // per stage: A 10240 + B 8704
#define F16_A_OFF 0
#define F16_B_OFF 10240
#define SMEM_F16 (2 * F16_BUF)
__global__ __launch_bounds__(256, 2)
void gemm_f16(const __half* __restrict__ A,
              int off0, int off1, int off2,
              __half* __restrict__ F0, __half* __restrict__ F1,
              __half* __restrict__ F2, int Nr) {
    extern __shared__ char smem[];
    int tid = threadIdx.x;
    int lane = tid & 31;
    int wid = tid >> 5;
    int warpM = wid & 3;
    int warpN = wid >> 2;
    int row0 = blockIdx.y * 128;
    int gi = blockIdx.x >> 1;
    int chf = blockIdx.x & 1;
    int boff = (gi == 0) ? off0 : ((gi == 1) ? off1 : off2);
    const __half* B = g_w_f16 + boff;
    __half* Ff = (gi == 0) ? F0 : ((gi == 1) ? F1 : F2);
    int col0 = chf * 128;

    float acc[2][8][4];
#pragma unroll
    for (int i = 0; i < 2; i++)
#pragma unroll
        for (int j = 0; j < 8; j++)
#pragma unroll
            for (int t = 0; t < 4; t++) acc[i][j][t] = 0.0f;

    int a_row = warpM * 32 + (lane & 15);
    int a_col8 = (lane >> 4) << 3;
    int b_row = lane & 15;
    int b_col = warpN * 64 + ((lane >> 4) << 3);

    int a_m = tid >> 1;
    int a_kq = (tid & 1) * 16;
    uint32_t a_sm = (uint32_t)(a_m * LDA_B + a_kq * 2);
    int b_kk = tid >> 3;
    int b_n0 = (tid & 7) * 16;
    uint32_t b_sm = (uint32_t)(b_kk * LDB_B + b_n0 * 2);
    int grow = row0 + a_m;
    int a_ok = (grow < Nr) ? 16 : 0;

    uint32_t sbase = (uint32_t)__cvta_generic_to_shared(smem);

#define F16_TILE(t)                                                          \
    do {                                                                     \
        int k0_ = (t) * 32;                                                  \
        uint32_t bb_ = sbase + ((t) & 1) * F16_BUF;                          \
        const char* gA = (const char*)(A + (size_t)grow * 256 + k0_ + a_kq); \
        cp16(bb_ + F16_A_OFF + a_sm,      gA,      a_ok);                    \
        cp16(bb_ + F16_A_OFF + a_sm + 16, gA + 16, a_ok);                    \
        const char* gB = (const char*)(B + (size_t)(k0_ + b_kk) * 256 + col0 + b_n0); \
        cp16(bb_ + F16_B_OFF + b_sm,      gB,      16);                      \
        cp16(bb_ + F16_B_OFF + b_sm + 16, gB + 16, 16);                      \
        asm volatile("cp.async.commit_group;");                              \
    } while (0)

    F16_TILE(0);
    for (int t = 0; t < 8; t++) {
        if (t + 1 < 8) {
            F16_TILE(t + 1);
            asm volatile("cp.async.wait_group 1;");
        } else {
            asm volatile("cp.async.wait_group 0;");
        }
        __syncthreads();
        uint32_t bb = sbase + (t & 1) * F16_BUF;
#pragma unroll
        for (int ks = 0; ks < 2; ks++) {
            unsigned ah[2][4], bh[4][4];
#pragma unroll
            for (int u = 0; u < 2; u++) {
                uint32_t ao = bb + F16_A_OFF +
                    (uint32_t)((a_row + u * 16) * LDA_B + (ks * 16 + a_col8) * 2);
                ldsm4(ah[u], ao);
            }
#pragma unroll
            for (int g = 0; g < 4; g++) {
                uint32_t bo = bb + F16_B_OFF +
                    (uint32_t)((ks * 16 + b_row) * LDB_B + (b_col + g * 16) * 2);
                ldsm4t(bh[g], bo);
            }
#pragma unroll
            for (int i = 0; i < 2; i++)
#pragma unroll
                for (int j = 0; j < 8; j++)
                    mma_f16(acc[i][j], ah[i], &bh[j >> 1][(j & 1) * 2]);
        }
        __syncthreads();
    }
#undef F16_TILE

#pragma unroll
    for (int i = 0; i < 2; i++) {
        int rbase = row0 + warpM * 32 + i * 16 + (lane >> 2);
#pragma unroll
        for (int j = 0; j < 8; j++) {
            int c = col0 + warpN * 64 + j * 8 + (lane & 3) * 2;
            if (rbase < Nr)
                *reinterpret_cast<__half2*>(&Ff[(size_t)rbase * 256 + c]) =
                    __floats2half2_rn(acc[i][j][0], acc[i][j][1]);
            if (rbase + 8 < Nr)
                *reinterpret_cast<__half2*>(&Ff[(size_t)(rbase + 8) * 256 + c]) =
                    __floats2half2_rn(acc[i][j][2], acc[i][j][3]);
        }
    }
}

// ============ fp16 single-term GEMM with concat-A / bias / relu =============
__global__ __launch_bounds__(256, 2)
void gemm_f16b(const __half* __restrict__ A1, const __half* __restrict__ A2,
               int boff, const float* __restrict__ bias,
               float* __restrict__ Cf, __half* __restrict__ Fo,
               int Nr, int Ktot, int relu) {
    extern __shared__ char smem[];
    int tid = threadIdx.x;
    int lane = tid & 31;
    int wid = tid >> 5;
    int warpM = wid & 3;
    int warpN = wid >> 2;
    int row0 = blockIdx.y * 128;
    int col0 = (blockIdx.x & 1) * 128;
    const __half* B = g_w_f16 + boff;

    float acc[2][8][4];
#pragma unroll
    for (int i = 0; i < 2; i++)
#pragma unroll
        for (int j = 0; j < 8; j++)
#pragma unroll
            for (int t = 0; t < 4; t++) acc[i][j][t] = 0.0f;

    int a_row = warpM * 32 + (lane & 15);
    int a_col8 = (lane >> 4) << 3;
    int b_row = lane & 15;
    int b_col = warpN * 64 + ((lane >> 4) << 3);

    int a_m = tid >> 1;
    int a_kq = (tid & 1) * 16;
    uint32_t a_sm = (uint32_t)(a_m * LDA_B + a_kq * 2);
    int b_kk = tid >> 3;
    int b_n0 = (tid & 7) * 16;
    uint32_t b_sm = (uint32_t)(b_kk * LDB_B + b_n0 * 2);
    int grow = row0 + a_m;
    int a_ok = (grow < Nr) ? 16 : 0;

    uint32_t sbase = (uint32_t)__cvta_generic_to_shared(smem);
    int T = Ktot >> 5;

#define F16B_TILE(t)                                                         \
    do {                                                                     \
        int k0_ = (t) * 32;                                                  \
        const __half* as_ = (k0_ < 256) ? A1 : A2;                           \
        int kb_ = k0_ & 255;                                                 \
        uint32_t bb_ = sbase + ((t) & 1) * F16_BUF;                          \
        const char* gA = (const char*)(as_ + (size_t)grow * 256 + kb_ + a_kq); \
        cp16(bb_ + F16_A_OFF + a_sm,      gA,      a_ok);                    \
        cp16(bb_ + F16_A_OFF + a_sm + 16, gA + 16, a_ok);                    \
        const char* gB = (const char*)(B + (size_t)(k0_ + b_kk) * 256 + col0 + b_n0); \
        cp16(bb_ + F16_B_OFF + b_sm,      gB,      16);                      \
        cp16(bb_ + F16_B_OFF + b_sm + 16, gB + 16, 16);                      \
        asm volatile("cp.async.commit_group;");                              \
    } while (0)

    F16B_TILE(0);
    for (int t = 0; t < T; t++) {
        if (t + 1 < T) {
            F16B_TILE(t + 1);
            asm volatile("cp.async.wait_group 1;");
        } else {
            asm volatile("cp.async.wait_group 0;");
        }
        __syncthreads();
        uint32_t bb = sbase + (t & 1) * F16_BUF;
#pragma unroll
        for (int ks = 0; ks < 2; ks++) {
            unsigned ah[2][4], bh[4][4];
#pragma unroll
            for (int u = 0; u < 2; u++) {
                uint32_t ao = bb + F16_A_OFF +
                    (uint32_t)((a_row + u * 16) * LDA_B + (ks * 16 + a_col8) * 2);
                ldsm4(ah[u], ao);
            }
#pragma unroll
            for (int g = 0; g < 4; g++) {
                uint32_t bo = bb + F16_B_OFF +
                    (uint32_t)((ks * 16 + b_row) * LDB_B + (b_col + g * 16) * 2);
                ldsm4t(bh[g], bo);
            }
#pragma unroll
            for (int i = 0; i < 2; i++)
#pragma unroll
                for (int j = 0; j < 8; j++)
                    mma_f16(acc[i][j], ah[i], &bh[j >> 1][(j & 1) * 2]);
        }
        __syncthreads();
    }
#undef F16B_TILE

#pragma unroll
    for (int i = 0; i < 2; i++) {
        int rbase = row0 + warpM * 32 + i * 16 + (lane >> 2);
#pragma unroll
        for (int j = 0; j < 8; j++) {
            int c = col0 + warpN * 64 + j * 8 + (lane & 3) * 2;
            float b0 = bias[c];
            float b1 = bias[c + 1];
            float v0 = acc[i][j][0] + b0;
            float v1 = acc[i][j][1] + b1;
            float v2 = acc[i][j][2] + b0;
            float v3 = acc[i][j][3] + b1;
            if (relu) {
                v0 = fmaxf(v0, 0.f); v1 = fmaxf(v1, 0.f);
                v2 = fmaxf(v2, 0.f); v3 = fmaxf(v3, 0.f);
            }
            if (Fo) {
                if (rbase < Nr)
                    *reinterpret_cast<__half2*>(&Fo[(size_t)rbase * 256 + c]) =
                        __floats2half2_rn(v0, v1);
                if (rbase + 8 < Nr)
                    *reinterpret_cast<__half2*>(&Fo[(size_t)(rbase + 8) * 256 + c]) =
                        __floats2half2_rn(v2, v3);
            } else {
                if (rbase < Nr)
                    *reinterpret_cast<float2*>(&Cf[(size_t)rbase * 256 + c]) =
                        make_float2(v0, v1);
                if (rbase + 8 < Nr)
                    *reinterpret_cast<float2*>(&Cf[(size_t)(rbase + 8) * 256 + c]) =
                        make_float2(v2, v3);
            }
        }
    }
}

// ====================== 3-term bf16 split-precision GEMM (head only) ========
#define BUF_BYTES 37888
#define A_H_OFF 0
#define A_L_OFF 10240
#define B_H_OFF 20480
#define B_L_OFF 29184
#define SMEM_BF16 (2 * BUF_BYTES)
__global__ __launch_bounds__(256, 2)
void gemm_bf16(const bf16* __restrict__ Ahi, const bf16* __restrict__ Alo,
               int boff,
               const float* __restrict__ bias,
               float* __restrict__ Cf,
               int Nr, int Ktot, int Mout, int relu) {
    extern __shared__ char smem[];
    int tid = threadIdx.x;
    int lane = tid & 31;
    int wid = tid >> 5;
    int warpM = wid & 3;
    int warpN = wid >> 2;
    int row0 = blockIdx.y * 128;
    int col0 = (Mout == 256) ? (blockIdx.x & 1) * 128 : 0;

    const bf16* Bh = g_w_hi + boff;
    const bf16* Bl = g_w_lo + boff;

    float acc[2][8][4];
#pragma unroll
    for (int i = 0; i < 2; i++)
#pragma unroll
        for (int j = 0; j < 8; j++)
#pragma unroll
            for (int t = 0; t < 4; t++) acc[i][j][t] = 0.0f;

    int a_row = warpM * 32 + (lane & 15);
    int a_col8 = (lane >> 4) << 3;
    int b_row = lane & 15;
    int b_col = warpN * 64 + ((lane >> 4) << 3);

    int a_m = tid >> 1;
    int a_kq = (tid & 1) * 16;
    uint32_t a_sm = (uint32_t)(a_m * LDA_B + a_kq * 2);
    int b_kk = tid >> 3;
    int b_n0 = (tid & 7) * 16;
    uint32_t b_sm = (uint32_t)(b_kk * LDB_B + b_n0 * 2);
    int grow = row0 + a_m;
    int a_ok = (grow < Nr) ? 16 : 0;

    uint32_t sbase = (uint32_t)__cvta_generic_to_shared(smem);
    int T = Ktot >> 5;

#define BF_TILE(t)                                                           \
    do {                                                                     \
        int k0_ = (t) * 32;                                                  \
        uint32_t bb_ = sbase + ((t) & 1) * BUF_BYTES;                        \
        const char* gAh = (const char*)(Ahi + (size_t)grow * 256 + k0_ + a_kq); \
        const char* gAl = (const char*)(Alo + (size_t)grow * 256 + k0_ + a_kq); \
        cp16(bb_ + A_H_OFF + a_sm,      gAh,      a_ok);                     \
        cp16(bb_ + A_H_OFF + a_sm + 16, gAh + 16, a_ok);                     \
        cp16(bb_ + A_L_OFF + a_sm,      gAl,      a_ok);                     \
        cp16(bb_ + A_L_OFF + a_sm + 16, gAl + 16, a_ok);                     \
        const char* gBh = (const char*)(Bh + (size_t)(k0_ + b_kk) * Mout + col0 + b_n0); \
        const char* gBl = (const char*)(Bl + (size_t)(k0_ + b_kk) * Mout + col0 + b_n0); \
        cp16(bb_ + B_H_OFF + b_sm,      gBh,      16);                       \
        cp16(bb_ + B_H_OFF + b_sm + 16, gBh + 16, 16);                       \
        cp16(bb_ + B_L_OFF + b_sm,      gBl,      16);                       \
        cp16(bb_ + B_L_OFF + b_sm + 16, gBl + 16, 16);                       \
        asm volatile("cp.async.commit_group;");                              \
    } while (0)

    BF_TILE(0);
    for (int t = 0; t < T; t++) {
        if (t + 1 < T) {
            BF_TILE(t + 1);
            asm volatile("cp.async.wait_group 1;");
        } else {
            asm volatile("cp.async.wait_group 0;");
        }
        __syncthreads();
        uint32_t bb = sbase + (t & 1) * BUF_BYTES;
#pragma unroll
        for (int ks = 0; ks < 2; ks++) {
            unsigned ah[2][4], al[2][4], bh[4][4], bl[4][4];
#pragma unroll
            for (int u = 0; u < 2; u++) {
                uint32_t ao = bb + (uint32_t)((a_row + u * 16) * LDA_B +
                                              (ks * 16 + a_col8) * 2);
                ldsm4(ah[u], ao + A_H_OFF);
                ldsm4(al[u], ao + A_L_OFF);
            }
#pragma unroll
            for (int g = 0; g < 4; g++) {
                uint32_t bo = bb + (uint32_t)((ks * 16 + b_row) * LDB_B +
                                              (b_col + g * 16) * 2);
                ldsm4t(bh[g], bo + B_H_OFF);
                ldsm4t(bl[g], bo + B_L_OFF);
            }
#pragma unroll
            for (int i = 0; i < 2; i++) {
#pragma unroll
                for (int j = 0; j < 8; j++) {
                    mma_bf16(acc[i][j], ah[i], &bh[j >> 1][(j & 1) * 2]);
                    mma_bf16(acc[i][j], ah[i], &bl[j >> 1][(j & 1) * 2]);
                    mma_bf16(acc[i][j], al[i], &bh[j >> 1][(j & 1) * 2]);
                }
            }
        }
        __syncthreads();
    }
#undef BF_TILE

#pragma unroll
    for (int i = 0; i < 2; i++) {
        int rbase = row0 + warpM * 32 + i * 16 + (lane >> 2);
#pragma unroll
        for (int j = 0; j < 8; j++) {
            int c = col0 + warpN * 64 + j * 8 + (lane & 3) * 2;
            float b0 = bias ? bias[c] : 0.0f;
            float b1 = bias ? bias[c + 1] : 0.0f;
            float v0 = acc[i][j][0] + b0;
            float v1 = acc[i][j][1] + b1;
            float v2 = acc[i][j][2] + b0;
            float v3 = acc[i][j][3] + b1;
            if (relu) {
                v0 = fmaxf(v0, 0.f); v1 = fmaxf(v1, 0.f);
                v2 = fmaxf(v2, 0.f); v3 = fmaxf(v3, 0.f);
            }
            if (rbase < Nr)
                *reinterpret_cast<float2*>(&Cf[(size_t)rbase * Mout + c]) =
                    make_float2(v0, v1);
            if (rbase + 8 < Nr)
                *reinterpret_cast<float2*>(
                    &Cf[(size_t)(rbase + 8) * Mout + c]) =
                    make_float2(v2, v3);
        }
    }
}

// ---------------- fused edge phase: logits + softmax + aggregate ------------
// One block (256 threads, 8 warps) per destination node; warp w = head w.
// Q row cached in smem; per-warp Q segment in registers; K gathered via uint4.
// Same op order as the old attn_kernel -> identical logits.
__device__ __forceinline__ float dot_u4(const uint4& qa, const uint4& ka,
                                        float acc) {
    const __half2* qh = reinterpret_cast<const __half2*>(&qa);
    const __half2* kh = reinterpret_cast<const __half2*>(&ka);
#pragma unroll
    for (int j = 0; j < 4; j++) {
        float2 qf = __half22float2(qh[j]);
        float2 kf = __half22float2(kh[j]);
        acc = fmaf(qf.x, kf.x, acc);
        acc = fmaf(qf.y, kf.y, acc);
    }
    return acc;
}

__global__ __launch_bounds__(256)
void edge_agg(const float* __restrict__ edge_attr,
              const float* __restrict__ We_l) {
    __shared__ __align__(16) __half s_q[HID];
    __shared__ float s_We[24];
    __shared__ int s_e[CAP];
    __shared__ int s_s[CAP];
    __shared__ float s_w[CAP * NHEAD];
    __shared__ float s_m[NHEAD], s_i[NHEAD];

    int n = blockIdx.x;
    int tid = threadIdx.x;
    int wid = tid >> 5;
    int lane = tid & 31;
    int row = g_rowstart[n];
    int deg = g_rowstart[n + 1] - row;
    int dcap = min(deg, CAP);

    s_q[tid] = g_qh[n * HID + tid];
    if (tid < 24) s_We[tid] = We_l[tid];
    for (int j = tid; j < dcap; j += 256) {
        int e = g_perm[row + j];
        s_e[j] = e;
        s_s[j] = g_src[e];
    }
    __syncthreads();

    // per-warp Q segment in registers (head wid)
    const uint4* qseg = reinterpret_cast<const uint4*>(s_q + wid * HDIM);
    uint4 q0 = qseg[0], q1 = qseg[1], q2 = qseg[2], q3 = qseg[3];
    float w0 = s_We[wid], w1 = s_We[8 + wid], w2 = s_We[16 + wid];

    // Phase A: logits + max
    float m = -3.4e38f;
    for (int j = lane; j < deg; j += 32) {
        int s, e;
        if (j < CAP) { s = s_s[j]; e = s_e[j]; }
        else         { e = g_perm[row + j]; s = g_src[e]; }
        const uint4* k4 =
            reinterpret_cast<const uint4*>(g_kh + s * HID + wid * HDIM);
        float acc = 0.0f;
        acc = dot_u4(q0, k4[0], acc);
        acc = dot_u4(q1, k4[1], acc);
        acc = dot_u4(q2, k4[2], acc);
        acc = dot_u4(q3, k4[3], acc);
        float eb = edge_attr[e * 3 + 0] * w0 + edge_attr[e * 3 + 1] * w1 +
                   edge_attr[e * 3 + 2] * w2;
        float a = acc * ATTN_SCALE + eb;
        a = (a > 0.0f) ? a : 0.2f * a;       // leaky_relu
        if (j < CAP) s_w[j * NHEAD + wid] = a;
        m = fmaxf(m, a);
    }
#pragma unroll
    for (int o = 16; o > 0; o >>= 1)
        m = fmaxf(m, __shfl_xor_sync(0xffffffffu, m, o));

    // Phase B: exp-sum + normalize
    float sum = 0.0f;
    for (int j = lane; j < dcap; j += 32) {
        float v = __expf(s_w[j * NHEAD + wid] - m);
        s_w[j * NHEAD + wid] = v;
        sum += v;
    }
    for (int j = CAP + lane; j < deg; j += 32) {   // never taken (deg << CAP)
        int e = g_perm[row + j];
        int s = g_src[e];
        const uint4* k4 =
            reinterpret_cast<const uint4*>(g_kh + s * HID + wid * HDIM);
        float acc = 0.0f;
        acc = dot_u4(q0, k4[0], acc);
        acc = dot_u4(q1, k4[1], acc);
        acc = dot_u4(q2, k4[2], acc);
        acc = dot_u4(q3, k4[3], acc);
        float eb = edge_attr[e * 3 + 0] * w0 + edge_attr[e * 3 + 1] * w1 +
                   edge_attr[e * 3 + 2] * w2;
        float a = acc * ATTN_SCALE + eb;
        a = (a > 0.0f) ? a : 0.2f * a;
        sum += __expf(a - m);
    }
#pragma unroll
    for (int o = 16; o > 0; o >>= 1)
        sum += __shfl_xor_sync(0xffffffffu, sum, o);
    float inv = (deg > 0) ? 1.0f / fmaxf(sum, 1e-12f) : 0.0f;
    for (int j = lane; j < dcap; j += 32)
        s_w[j * NHEAD + wid] *= inv;
    if (lane == 0) { s_m[wid] = m; s_i[wid] = inv; }
    __syncthreads();

    // Phase C: weighted V aggregation (channel c = tid, head = c>>5)
    int nh = tid >> 5;
    float acc = 0.0f;
    for (int j = 0; j < dcap; j++)
        acc += s_w[j * NHEAD + nh] * __half2float(g_vh[s_s[j] * HID + tid]);
    for (int j = CAP; j < deg; j++) {              // never taken
        int e = g_perm[row + j];
        int s = g_src[e];
        const uint4* k4 =
            reinterpret_cast<const uint4*>(g_kh + s * HID + nh * HDIM);
        const uint4* qf =
            reinterpret_cast<const uint4*>(s_q + nh * HDIM);
        float d2 = 0.0f;
        d2 = dot_u4(qf[0], k4[0], d2);
        d2 = dot_u4(qf[1], k4[1], d2);
        d2 = dot_u4(qf[2], k4[2], d2);
        d2 = dot_u4(qf[3], k4[3], d2);
        float eb = edge_attr[e * 3 + 0] * s_We[nh] +
                   edge_attr[e * 3 + 1] * s_We[8 + nh] +
                   edge_attr[e * 3 + 2] * s_We[16 + nh];
        float a = d2 * ATTN_SCALE + eb;
        a = (a > 0.0f) ? a : 0.2f * a;
        float w = __expf(a - s_m[nh]) * s_i[nh];
        acc += w * __half2float(g_vh[s * HID + tid]);
    }
    g_agg_f16[n * HID + tid] = __float2half(acc);
}

// ---------------- residual + LayerNorm: h = LN(h + upd)*gamma + beta --------
__global__ void ln_kernel(const float* __restrict__ upd,
                          const float* __restrict__ gamma_l,
                          const float* __restrict__ beta_l, int last) {
    int n = blockIdx.x;
    int t = threadIdx.x;   // 256
    float x = g_h[n * HID + t] + upd[n * HID + t];
    __shared__ float s1[8], s2[8];
    float a = x, b = x * x;
#pragma unroll
    for (int o = 16; o > 0; o >>= 1) {
        a += __shfl_down_sync(0xffffffffu, a, o);
        b += __shfl_down_sync(0xffffffffu, b, o);
    }
    int warp = t >> 5, lane = t & 31;
    if (lane == 0) { s1[warp] = a; s2[warp] = b; }
    __syncthreads();
    if (warp == 0) {
        a = (lane < 8) ? s1[lane] : 0.0f;
        b = (lane < 8) ? s2[lane] : 0.0f;
#pragma unroll
        for (int o = 4; o > 0; o >>= 1) {
            a += __shfl_down_sync(0xffffffffu, a, o);
            b += __shfl_down_sync(0xffffffffu, b, o);
        }
        if (lane == 0) { s1[0] = a; s2[0] = b; }
    }
    __syncthreads();
    float mu = s1[0] * (1.0f / HID);
    float var = s2[0] * (1.0f / HID) - mu * mu;
    float r = (x - mu) * rsqrtf(var + 1e-5f) * gamma_l[t] + beta_l[t];
    g_h[n * HID + t] = r;
    g_h_f16[n * HID + t] = __float2half(r);
    if (last) {
        bf16 hi, lo;
        split_bf16(r, hi, lo);
        g_h_hi[n * HID + t] = hi;
        g_h_lo[n * HID + t] = lo;
    }
}

// ---------------- output head 2: out = hidden(N,128) @ W2(128,1) + b2 -------
__global__ void head2_kernel(const float* __restrict__ hidden,
                             const float* __restrict__ W2,
                             const float* __restrict__ b2,
                             float* __restrict__ out) {
    int gw = (blockIdx.x * blockDim.x + threadIdx.x) >> 5;
    int lane = threadIdx.x & 31;
    if (gw >= N_NODES) return;
    float acc = 0.0f;
#pragma unroll
    for (int i = 0; i < 4; i++) {
        int c = lane + i * 32;
        acc += hidden[gw * 128 + c] * W2[c];
    }
#pragma unroll
    for (int o = 16; o > 0; o >>= 1)
        acc += __shfl_down_sync(0xffffffffu, acc, o);
    if (lane == 0) out[gw] = acc + b2[0];
}

// ---------------- launch ----------------------------------------------------
extern "C" void kernel_launch(void* const* d_in, const int* in_sizes, int n_in,
                              void* d_out, int out_size) {
    const float* x         = (const float*)d_in[0];
    const float* edge_attr = (const float*)d_in[1];
    const float* W_in      = (const float*)d_in[2];
    const float* b_in      = (const float*)d_in[3];
    const float* Wq        = (const float*)d_in[4];
    const float* Wk        = (const float*)d_in[5];
    const float* Wv        = (const float*)d_in[6];
    const float* We        = (const float*)d_in[7];
    const float* Wo        = (const float*)d_in[8];
    const float* bo        = (const float*)d_in[9];
    const float* Wm        = (const float*)d_in[10];
    const float* bm        = (const float*)d_in[11];
    const float* gamma     = (const float*)d_in[12];
    const float* beta      = (const float*)d_in[13];
    const float* Wh1       = (const float*)d_in[14];
    const float* bh1       = (const float*)d_in[15];
    const float* Wh2       = (const float*)d_in[16];
    const float* bh2       = (const float*)d_in[17];
    const int*   ei_raw    = (const int*)d_in[18];

    bf16 *phhi, *phlo;
    float *pupd, *phid;
    __half *pqh, *pkh, *pvh, *phf16, *pagg16, *pao16;
    cudaGetSymbolAddress((void**)&phhi,   g_h_hi);
    cudaGetSymbolAddress((void**)&phlo,   g_h_lo);
    cudaGetSymbolAddress((void**)&pupd,   g_upd);
    cudaGetSymbolAddress((void**)&phid,   g_hid);
    cudaGetSymbolAddress((void**)&pqh,    g_qh);
    cudaGetSymbolAddress((void**)&pkh,    g_kh);
    cudaGetSymbolAddress((void**)&pvh,    g_vh);
    cudaGetSymbolAddress((void**)&phf16,  g_h_f16);
    cudaGetSymbolAddress((void**)&pagg16, g_agg_f16);
    cudaGetSymbolAddress((void**)&pao16,  g_ao_f16);

    cudaFuncSetAttribute(gemm_f16, cudaFuncAttributeMaxDynamicSharedMemorySize,
                         SMEM_F16);
    cudaFuncSetAttribute(gemm_f16b, cudaFuncAttributeMaxDynamicSharedMemorySize,
                         SMEM_F16);
    cudaFuncSetAttribute(gemm_bf16, cudaFuncAttributeMaxDynamicSharedMemorySize,
                         SMEM_BF16);

    const int NH_ELEMS = N_NODES * HID;

    // decode edge indices + build CSR (by dst)
    detect_idx<<<1, 256>>>(ei_raw);
    convert_idx<<<(N_EDGES + 255) / 256, 256>>>(ei_raw);
    zero_cnt<<<(N_NODES + 255) / 256, 256>>>();
    count_deg<<<(N_EDGES + 255) / 256, 256>>>();
    scan_rowstart<<<1, 1024>>>();
    copy_cursor<<<(N_NODES + 255) / 256, 256>>>();
    scatter_perm<<<(N_EDGES + 255) / 256, 256>>>();

    // pre-convert weights (QKV/Wo/Wm also to fp16)
    convert_w<<<(196608 + 255) / 256, 256>>>(Wq, 196608, OFF_WQ, 1);
    convert_w<<<(196608 + 255) / 256, 256>>>(Wk, 196608, OFF_WK, 1);
    convert_w<<<(196608 + 255) / 256, 256>>>(Wv, 196608, OFF_WV, 1);
    convert_w<<<(196608 + 255) / 256, 256>>>(Wo, 196608, OFF_WO, 1);
    convert_w<<<(393216 + 255) / 256, 256>>>(Wm, 393216, OFF_WM, 1);
    convert_w<<<(32768 + 255) / 256, 256>>>(Wh1, 32768, OFF_WH1, 0);

    input_proj<<<(NH_ELEMS + 255) / 256, 256>>>(x, W_in, b_in);

    int rows = (N_NODES + 127) / 128;   // 391
    dim3 gridQKV(6, rows);
    dim3 grid1(2, rows);
    dim3 gridHead(1, rows);

    for (int l = 0; l < NLAYER; l++) {
        int offQ = OFF_WQ + l * 65536;
        int offK = OFF_WK + l * 65536;
        int offV = OFF_WV + l * 65536;
        int offO = OFF_WO + l * 65536;
        int offM = OFF_WM + l * 131072;
        const float* We_l = We + l * 3 * NHEAD;
        const float* bo_l = bo + l * HID;
        const float* bm_l = bm + l * HID;
        const float* ga_l = gamma + l * HID;
        const float* be_l = beta + l * HID;

        // fused QKV: dedicated fp16 single-term kernel
        gemm_f16<<<gridQKV, 256, SMEM_F16>>>(phf16, offQ, offK, offV,
                                             pqh, pkh, pvh, N_NODES);

        // fused edge phase: logits + softmax + aggregate (-> fp16 agg)
        edge_agg<<<N_NODES, 256>>>(edge_attr, We_l);

        // aggO = agg @ Wo + bo  -> fp16
        gemm_f16b<<<grid1, 256, SMEM_F16>>>(
            pagg16, nullptr, offO, bo_l, nullptr, pao16, N_NODES, 256, 0);
        // upd = relu(concat([h, aggO]) @ Wm + bm)  -> fp32
        gemm_f16b<<<grid1, 256, SMEM_F16>>>(
            phf16, pao16, offM, bm_l, pupd, nullptr, N_NODES, 512, 1);
        // h = LN(h + upd) * gamma + beta  (hi/lo only on last layer)
        ln_kernel<<<N_NODES, 256>>>(pupd, ga_l, be_l, l == NLAYER - 1);
    }

    // head: hidden = relu(h @ Wh1 + bh1) -> fp32 (3-term bf16 for accuracy)
    gemm_bf16<<<gridHead, 256, SMEM_BF16>>>(
        phhi, phlo, OFF_WH1, bh1, phid, N_NODES, 256, 128, 1);
    head2_kernel<<<(N_NODES * 32 + 255) / 256, 256>>>(phid, Wh2, bh2,
                                                      (float*)d_out);
}

// round 17
// speedup vs baseline: 1.7508x; 1.7508x over previous
#include <cuda_runtime.h>
#include <cuda_bf16.h>
#include <cuda_fp16.h>
#include <math.h>
#include <stdint.h>

#define N_NODES 50000
#define N_EDGES 800000
#define HID 256
#define NHEAD 8
#define HDIM 32
#define NLAYER 3
#define ATTN_SCALE 0.17677669529663687f   // 32^-0.5
#define CAP 512                            // per-node smem edge capacity

typedef __nv_bfloat16 bf16;

// ---------------- scratch (static device globals; no allocs allowed) --------
__device__ float g_h[N_NODES * HID];       // fp32 h (LN residual)
__device__ bf16  g_h_hi[N_NODES * HID];    // h split (head GEMM only)
__device__ bf16  g_h_lo[N_NODES * HID];
__device__ __half g_h_f16[N_NODES * HID];  // h fp16 (QKV + Wm GEMM A)
__device__ __half g_agg_f16[N_NODES * HID];// agg fp16 (Wo GEMM A)
__device__ __half g_ao_f16[N_NODES * HID]; // aggO fp16 (Wm GEMM A2)
__device__ float g_upd[N_NODES * HID];     // Wm output (fp32)
__device__ float g_hid[N_NODES * HID];     // head hidden (fp32, 128 used)
__device__ __half g_qh[N_NODES * HID];     // Q fp16
__device__ __half g_kh[N_NODES * HID];     // K fp16
__device__ __half g_vh[N_NODES * HID];     // V fp16
__device__ float g_attn[N_EDGES * NHEAD];  // raw leaky logits (edge-indexed)
__device__ int g_src[N_EDGES];
__device__ int g_dst[N_EDGES];
__device__ int g_perm[N_EDGES];            // edges sorted by dst (CSR)
__device__ int g_rowstart[N_NODES + 1];
__device__ int g_cnt[N_NODES];
__device__ int g_cursor[N_NODES];
__device__ int g_is64;

// pre-converted weights
#define OFF_WQ 0
#define OFF_WK 196608
#define OFF_WV 393216
#define OFF_WO 589824
#define OFF_WM 983040
#define OFF_WH1 1376256
#define W_TOTAL 1409024
__device__ bf16 g_w_hi[W_TOTAL];
__device__ bf16 g_w_lo[W_TOTAL];
__device__ __half g_w_f16[W_TOTAL];        // fp16 copy (QKV/Wo/Wm regions)

__device__ __forceinline__ void split_bf16(float v, bf16& hi, bf16& lo) {
    hi = __float2bfloat16(v);
    lo = __float2bfloat16(v - __bfloat162float(hi));
}

// ---------------- index dtype detection + conversion ------------------------
__global__ void detect_idx(const int* __restrict__ raw) {
    __shared__ int any;
    if (threadIdx.x == 0) any = 0;
    __syncthreads();
    for (int i = threadIdx.x; i < 2048; i += blockDim.x)
        if (raw[2 * i + 1] != 0) any = 1;
    __syncthreads();
    if (threadIdx.x == 0) g_is64 = any ? 0 : 1;
}

__global__ void convert_idx(const int* __restrict__ raw) {
    int e = blockIdx.x * blockDim.x + threadIdx.x;
    if (e >= N_EDGES) return;
    int s, d;
    if (g_is64) {
        s = raw[2 * e];
        d = raw[2 * (N_EDGES + e)];
    } else {
        s = raw[e];
        d = raw[N_EDGES + e];
    }
    s = min(max(s, 0), N_NODES - 1);
    d = min(max(d, 0), N_NODES - 1);
    g_src[e] = s;
    g_dst[e] = d;
}

// ---------------- weight pre-conversion -------------------------------------
__global__ void convert_w(const float* __restrict__ src, int n, int off,
                          int f16) {
    int i = blockIdx.x * blockDim.x + threadIdx.x;
    if (i >= n) return;
    float v = src[i];
    bf16 hi, lo;
    split_bf16(v, hi, lo);
    g_w_hi[off + i] = hi;
    g_w_lo[off + i] = lo;
    if (f16) g_w_f16[off + i] = __float2half(v);
}

// ---------------- CSR build --------------------------------------------------
__global__ void zero_cnt() {
    int i = blockIdx.x * blockDim.x + threadIdx.x;
    if (i < N_NODES) g_cnt[i] = 0;
}

__global__ void count_deg() {
    int e = blockIdx.x * blockDim.x + threadIdx.x;
    if (e >= N_EDGES) return;
    atomicAdd(&g_cnt[g_dst[e]], 1);
}

__global__ void scan_rowstart() {     // 1 block, 1024 threads
    __shared__ int sm[1024];
    int t = threadIdx.x;
    int run = 0;
    for (int base = 0; base < N_NODES; base += 1024) {
        int idx = base + t;
        int v = (idx < N_NODES) ? g_cnt[idx] : 0;
        sm[t] = v;
        __syncthreads();
        for (int off = 1; off < 1024; off <<= 1) {
            int x = (t >= off) ? sm[t - off] : 0;
            __syncthreads();
            sm[t] += x;
            __syncthreads();
        }
        if (idx < N_NODES) g_rowstart[idx] = run + sm[t] - v;
        run += sm[1023];
        __syncthreads();
    }
    if (t == 0) g_rowstart[N_NODES] = run;
}

__global__ void copy_cursor() {
    int i = blockIdx.x * blockDim.x + threadIdx.x;
    if (i < N_NODES) g_cursor[i] = g_rowstart[i];
}

__global__ void scatter_perm() {
    int e = blockIdx.x * blockDim.x + threadIdx.x;
    if (e >= N_EDGES) return;
    int pos = atomicAdd(&g_cursor[g_dst[e]], 1);
    g_perm[pos] = e;
}

// ---------------- input projection: h = relu(x @ W_in + b_in) ---------------
__global__ void input_proj(const float* __restrict__ x,
                           const float* __restrict__ W,
                           const float* __restrict__ b) {
    int idx = blockIdx.x * blockDim.x + threadIdx.x;
    if (idx >= N_NODES * HID) return;
    int n = idx >> 8;
    int j = idx & 255;
    float acc = b[j];
#pragma unroll
    for (int f = 0; f < 10; f++) acc += x[n * 10 + f] * W[f * HID + j];
    float r = fmaxf(acc, 0.0f);
    g_h[idx] = r;
    g_h_f16[idx] = __float2half(r);
}

// ---------------- tensor-core GEMM helpers -----------------------------------
__device__ __forceinline__ void mma_bf16(float* c, const unsigned* a,
                                         const unsigned* b) {
    asm volatile(
        "mma.sync.aligned.m16n8k16.row.col.f32.bf16.bf16.f32 "
        "{%0,%1,%2,%3}, {%4,%5,%6,%7}, {%8,%9}, {%0,%1,%2,%3};\n"
        : "+f"(c[0]), "+f"(c[1]), "+f"(c[2]), "+f"(c[3])
        : "r"(a[0]), "r"(a[1]), "r"(a[2]), "r"(a[3]), "r"(b[0]), "r"(b[1]));
}
__device__ __forceinline__ void mma_f16(float* c, const unsigned* a,
                                        const unsigned* b) {
    asm volatile(
        "mma.sync.aligned.m16n8k16.row.col.f32.f16.f16.f32 "
        "{%0,%1,%2,%3}, {%4,%5,%6,%7}, {%8,%9}, {%0,%1,%2,%3};\n"
        : "+f"(c[0]), "+f"(c[1]), "+f"(c[2]), "+f"(c[3])
        : "r"(a[0]), "r"(a[1]), "r"(a[2]), "r"(a[3]), "r"(b[0]), "r"(b[1]));
}
__device__ __forceinline__ void ldsm4(unsigned* r, unsigned addr) {
    asm volatile(
        "ldmatrix.sync.aligned.m8n8.x4.shared.b16 {%0,%1,%2,%3}, [%4];\n"
        : "=r"(r[0]), "=r"(r[1]), "=r"(r[2]), "=r"(r[3]) : "r"(addr));
}
__device__ __forceinline__ void ldsm4t(unsigned* r, unsigned addr) {
    asm volatile(
        "ldmatrix.sync.aligned.m8n8.x4.trans.shared.b16 {%0,%1,%2,%3}, [%4];\n"
        : "=r"(r[0]), "=r"(r[1]), "=r"(r[2]), "=r"(r[3]) : "r"(addr));
}
__device__ __forceinline__ void cp16(uint32_t dst, const void* src, int sz) {
    asm volatile("cp.async.cg.shared.global [%0], [%1], 16, %2;"
                 :: "r"(dst), "l"(src), "r"(sz));
}

#define LDA_B 80      // A row stride bytes (40 halves)
#define LDB_B 272     // B row stride bytes (136 halves)

// ====================== fp16 single-term QKV GEMM ===========================
#define F16_BUF 18944               // per stage: A 10240 + B 8704
#define F16_A_OFF 0
#define F16_B_OFF 10240
#define SMEM_F16 (2 * F16_BUF)
__global__ __launch_bounds__(256, 2)
void gemm_f16(const __half* __restrict__ A,
              int off0, int off1, int off2,
              __half* __restrict__ F0, __half* __restrict__ F1,
              __half* __restrict__ F2, int Nr) {
    extern __shared__ char smem[];
    int tid = threadIdx.x;
    int lane = tid & 31;
    int wid = tid >> 5;
    int warpM = wid & 3;
    int warpN = wid >> 2;
    int row0 = blockIdx.y * 128;
    int gi = blockIdx.x >> 1;
    int chf = blockIdx.x & 1;
    int boff = (gi == 0) ? off0 : ((gi == 1) ? off1 : off2);
    const __half* B = g_w_f16 + boff;
    __half* Ff = (gi == 0) ? F0 : ((gi == 1) ? F1 : F2);
    int col0 = chf * 128;

    float acc[2][8][4];
#pragma unroll
    for (int i = 0; i < 2; i++)
#pragma unroll
        for (int j = 0; j < 8; j++)
#pragma unroll
            for (int t = 0; t < 4; t++) acc[i][j][t] = 0.0f;

    int a_row = warpM * 32 + (lane & 15);
    int a_col8 = (lane >> 4) << 3;
    int b_row = lane & 15;
    int b_col = warpN * 64 + ((lane >> 4) << 3);

    int a_m = tid >> 1;
    int a_kq = (tid & 1) * 16;
    uint32_t a_sm = (uint32_t)(a_m * LDA_B + a_kq * 2);
    int b_kk = tid >> 3;
    int b_n0 = (tid & 7) * 16;
    uint32_t b_sm = (uint32_t)(b_kk * LDB_B + b_n0 * 2);
    int grow = row0 + a_m;
    int a_ok = (grow < Nr) ? 16 : 0;

    uint32_t sbase = (uint32_t)__cvta_generic_to_shared(smem);

#define F16_TILE(t)                                                          \
    do {                                                                     \
        int k0_ = (t) * 32;                                                  \
        uint32_t bb_ = sbase + ((t) & 1) * F16_BUF;                          \
        const char* gA = (const char*)(A + (size_t)grow * 256 + k0_ + a_kq); \
        cp16(bb_ + F16_A_OFF + a_sm,      gA,      a_ok);                    \
        cp16(bb_ + F16_A_OFF + a_sm + 16, gA + 16, a_ok);                    \
        const char* gB = (const char*)(B + (size_t)(k0_ + b_kk) * 256 + col0 + b_n0); \
        cp16(bb_ + F16_B_OFF + b_sm,      gB,      16);                      \
        cp16(bb_ + F16_B_OFF + b_sm + 16, gB + 16, 16);                      \
        asm volatile("cp.async.commit_group;");                              \
    } while (0)

    F16_TILE(0);
    for (int t = 0; t < 8; t++) {
        if (t + 1 < 8) {
            F16_TILE(t + 1);
            asm volatile("cp.async.wait_group 1;");
        } else {
            asm volatile("cp.async.wait_group 0;");
        }
        __syncthreads();
        uint32_t bb = sbase + (t & 1) * F16_BUF;
#pragma unroll
        for (int ks = 0; ks < 2; ks++) {
            unsigned ah[2][4], bh[4][4];
#pragma unroll
            for (int u = 0; u < 2; u++) {
                uint32_t ao = bb + F16_A_OFF +
                    (uint32_t)((a_row + u * 16) * LDA_B + (ks * 16 + a_col8) * 2);
                ldsm4(ah[u], ao);
            }
#pragma unroll
            for (int g = 0; g < 4; g++) {
                uint32_t bo = bb + F16_B_OFF +
                    (uint32_t)((ks * 16 + b_row) * LDB_B + (b_col + g * 16) * 2);
                ldsm4t(bh[g], bo);
            }
#pragma unroll
            for (int i = 0; i < 2; i++)
#pragma unroll
                for (int j = 0; j < 8; j++)
                    mma_f16(acc[i][j], ah[i], &bh[j >> 1][(j & 1) * 2]);
        }
        __syncthreads();
    }
#undef F16_TILE

#pragma unroll
    for (int i = 0; i < 2; i++) {
        int rbase = row0 + warpM * 32 + i * 16 + (lane >> 2);
#pragma unroll
        for (int j = 0; j < 8; j++) {
            int c = col0 + warpN * 64 + j * 8 + (lane & 3) * 2;
            if (rbase < Nr)
                *reinterpret_cast<__half2*>(&Ff[(size_t)rbase * 256 + c]) =
                    __floats2half2_rn(acc[i][j][0], acc[i][j][1]);
            if (rbase + 8 < Nr)
                *reinterpret_cast<__half2*>(&Ff[(size_t)(rbase + 8) * 256 + c]) =
                    __floats2half2_rn(acc[i][j][2], acc[i][j][3]);
        }
    }
}

// ============ fp16 single-term GEMM with concat-A / bias / relu =============
__global__ __launch_bounds__(256, 2)
void gemm_f16b(const __half* __restrict__ A1, const __half* __restrict__ A2,
               int boff, const float* __restrict__ bias,
               float* __restrict__ Cf, __half* __restrict__ Fo,
               int Nr, int Ktot, int relu) {
    extern __shared__ char smem[];
    int tid = threadIdx.x;
    int lane = tid & 31;
    int wid = tid >> 5;
    int warpM = wid & 3;
    int warpN = wid >> 2;
    int row0 = blockIdx.y * 128;
    int col0 = (blockIdx.x & 1) * 128;
    const __half* B = g_w_f16 + boff;

    float acc[2][8][4];
#pragma unroll
    for (int i = 0; i < 2; i++)
#pragma unroll
        for (int j = 0; j < 8; j++)
#pragma unroll
            for (int t = 0; t < 4; t++) acc[i][j][t] = 0.0f;

    int a_row = warpM * 32 + (lane & 15);
    int a_col8 = (lane >> 4) << 3;
    int b_row = lane & 15;
    int b_col = warpN * 64 + ((lane >> 4) << 3);

    int a_m = tid >> 1;
    int a_kq = (tid & 1) * 16;
    uint32_t a_sm = (uint32_t)(a_m * LDA_B + a_kq * 2);
    int b_kk = tid >> 3;
    int b_n0 = (tid & 7) * 16;
    uint32_t b_sm = (uint32_t)(b_kk * LDB_B + b_n0 * 2);
    int grow = row0 + a_m;
    int a_ok = (grow < Nr) ? 16 : 0;

    uint32_t sbase = (uint32_t)__cvta_generic_to_shared(smem);
    int T = Ktot >> 5;

#define F16B_TILE(t)                                                         \
    do {                                                                     \
        int k0_ = (t) * 32;                                                  \
        const __half* as_ = (k0_ < 256) ? A1 : A2;                           \
        int kb_ = k0_ & 255;                                                 \
        uint32_t bb_ = sbase + ((t) & 1) * F16_BUF;                          \
        const char* gA = (const char*)(as_ + (size_t)grow * 256 + kb_ + a_kq); \
        cp16(bb_ + F16_A_OFF + a_sm,      gA,      a_ok);                    \
        cp16(bb_ + F16_A_OFF + a_sm + 16, gA + 16, a_ok);                    \
        const char* gB = (const char*)(B + (size_t)(k0_ + b_kk) * 256 + col0 + b_n0); \
        cp16(bb_ + F16_B_OFF + b_sm,      gB,      16);                      \
        cp16(bb_ + F16_B_OFF + b_sm + 16, gB + 16, 16);                      \
        asm volatile("cp.async.commit_group;");                              \
    } while (0)

    F16B_TILE(0);
    for (int t = 0; t < T; t++) {
        if (t + 1 < T) {
            F16B_TILE(t + 1);
            asm volatile("cp.async.wait_group 1;");
        } else {
            asm volatile("cp.async.wait_group 0;");
        }
        __syncthreads();
        uint32_t bb = sbase + (t & 1) * F16_BUF;
#pragma unroll
        for (int ks = 0; ks < 2; ks++) {
            unsigned ah[2][4], bh[4][4];
#pragma unroll
            for (int u = 0; u < 2; u++) {
                uint32_t ao = bb + F16_A_OFF +
                    (uint32_t)((a_row + u * 16) * LDA_B + (ks * 16 + a_col8) * 2);
                ldsm4(ah[u], ao);
            }
#pragma unroll
            for (int g = 0; g < 4; g++) {
                uint32_t bo = bb + F16_B_OFF +
                    (uint32_t)((ks * 16 + b_row) * LDB_B + (b_col + g * 16) * 2);
                ldsm4t(bh[g], bo);
            }
#pragma unroll
            for (int i = 0; i < 2; i++)
#pragma unroll
                for (int j = 0; j < 8; j++)
                    mma_f16(acc[i][j], ah[i], &bh[j >> 1][(j & 1) * 2]);
        }
        __syncthreads();
    }
#undef F16B_TILE

#pragma unroll
    for (int i = 0; i < 2; i++) {
        int rbase = row0 + warpM * 32 + i * 16 + (lane >> 2);
#pragma unroll
        for (int j = 0; j < 8; j++) {
            int c = col0 + warpN * 64 + j * 8 + (lane & 3) * 2;
            float b0 = bias[c];
            float b1 = bias[c + 1];
            float v0 = acc[i][j][0] + b0;
            float v1 = acc[i][j][1] + b1;
            float v2 = acc[i][j][2] + b0;
            float v3 = acc[i][j][3] + b1;
            if (relu) {
                v0 = fmaxf(v0, 0.f); v1 = fmaxf(v1, 0.f);
                v2 = fmaxf(v2, 0.f); v3 = fmaxf(v3, 0.f);
            }
            if (Fo) {
                if (rbase < Nr)
                    *reinterpret_cast<__half2*>(&Fo[(size_t)rbase * 256 + c]) =
                        __floats2half2_rn(v0, v1);
                if (rbase + 8 < Nr)
                    *reinterpret_cast<__half2*>(&Fo[(size_t)(rbase + 8) * 256 + c]) =
                        __floats2half2_rn(v2, v3);
            } else {
                if (rbase < Nr)
                    *reinterpret_cast<float2*>(&Cf[(size_t)rbase * 256 + c]) =
                        make_float2(v0, v1);
                if (rbase + 8 < Nr)
                    *reinterpret_cast<float2*>(&Cf[(size_t)(rbase + 8) * 256 + c]) =
                        make_float2(v2, v3);
            }
        }
    }
}

// ====================== 3-term bf16 split-precision GEMM (head only) ========
#define BUF_BYTES 37888
#define A_H_OFF 0
#define A_L_OFF 10240
#define B_H_OFF 20480
#define B_L_OFF 29184
#define SMEM_BF16 (2 * BUF_BYTES)
__global__ __launch_bounds__(256, 2)
void gemm_bf16(const bf16* __restrict__ Ahi, const bf16* __restrict__ Alo,
               int boff,
               const float* __restrict__ bias,
               float* __restrict__ Cf,
               int Nr, int Ktot, int Mout, int relu) {
    extern __shared__ char smem[];
    int tid = threadIdx.x;
    int lane = tid & 31;
    int wid = tid >> 5;
    int warpM = wid & 3;
    int warpN = wid >> 2;
    int row0 = blockIdx.y * 128;
    int col0 = (Mout == 256) ? (blockIdx.x & 1) * 128 : 0;

    const bf16* Bh = g_w_hi + boff;
    const bf16* Bl = g_w_lo + boff;

    float acc[2][8][4];
#pragma unroll
    for (int i = 0; i < 2; i++)
#pragma unroll
        for (int j = 0; j < 8; j++)
#pragma unroll
            for (int t = 0; t < 4; t++) acc[i][j][t] = 0.0f;

    int a_row = warpM * 32 + (lane & 15);
    int a_col8 = (lane >> 4) << 3;
    int b_row = lane & 15;
    int b_col = warpN * 64 + ((lane >> 4) << 3);

    int a_m = tid >> 1;
    int a_kq = (tid & 1) * 16;
    uint32_t a_sm = (uint32_t)(a_m * LDA_B + a_kq * 2);
    int b_kk = tid >> 3;
    int b_n0 = (tid & 7) * 16;
    uint32_t b_sm = (uint32_t)(b_kk * LDB_B + b_n0 * 2);
    int grow = row0 + a_m;
    int a_ok = (grow < Nr) ? 16 : 0;

    uint32_t sbase = (uint32_t)__cvta_generic_to_shared(smem);
    int T = Ktot >> 5;

#define BF_TILE(t)                                                           \
    do {                                                                     \
        int k0_ = (t) * 32;                                                  \
        uint32_t bb_ = sbase + ((t) & 1) * BUF_BYTES;                        \
        const char* gAh = (const char*)(Ahi + (size_t)grow * 256 + k0_ + a_kq); \
        const char* gAl = (const char*)(Alo + (size_t)grow * 256 + k0_ + a_kq); \
        cp16(bb_ + A_H_OFF + a_sm,      gAh,      a_ok);                     \
        cp16(bb_ + A_H_OFF + a_sm + 16, gAh + 16, a_ok);                     \
        cp16(bb_ + A_L_OFF + a_sm,      gAl,      a_ok);                     \
        cp16(bb_ + A_L_OFF + a_sm + 16, gAl + 16, a_ok);                     \
        const char* gBh = (const char*)(Bh + (size_t)(k0_ + b_kk) * Mout + col0 + b_n0); \
        const char* gBl = (const char*)(Bl + (size_t)(k0_ + b_kk) * Mout + col0 + b_n0); \
        cp16(bb_ + B_H_OFF + b_sm,      gBh,      16);                       \
        cp16(bb_ + B_H_OFF + b_sm + 16, gBh + 16, 16);                       \
        cp16(bb_ + B_L_OFF + b_sm,      gBl,      16);                       \
        cp16(bb_ + B_L_OFF + b_sm + 16, gBl + 16, 16);                       \
        asm volatile("cp.async.commit_group;");                              \
    } while (0)

    BF_TILE(0);
    for (int t = 0; t < T; t++) {
        if (t + 1 < T) {
            BF_TILE(t + 1);
            asm volatile("cp.async.wait_group 1;");
        } else {
            asm volatile("cp.async.wait_group 0;");
        }
        __syncthreads();
        uint32_t bb = sbase + (t & 1) * BUF_BYTES;
#pragma unroll
        for (int ks = 0; ks < 2; ks++) {
            unsigned ah[2][4], al[2][4], bh[4][4], bl[4][4];
#pragma unroll
            for (int u = 0; u < 2; u++) {
                uint32_t ao = bb + (uint32_t)((a_row + u * 16) * LDA_B +
                                              (ks * 16 + a_col8) * 2);
                ldsm4(ah[u], ao + A_H_OFF);
                ldsm4(al[u], ao + A_L_OFF);
            }
#pragma unroll
            for (int g = 0; g < 4; g++) {
                uint32_t bo = bb + (uint32_t)((ks * 16 + b_row) * LDB_B +
                                              (b_col + g * 16) * 2);
                ldsm4t(bh[g], bo + B_H_OFF);
                ldsm4t(bl[g], bo + B_L_OFF);
            }
#pragma unroll
            for (int i = 0; i < 2; i++) {
#pragma unroll
                for (int j = 0; j < 8; j++) {
                    mma_bf16(acc[i][j], ah[i], &bh[j >> 1][(j & 1) * 2]);
                    mma_bf16(acc[i][j], ah[i], &bl[j >> 1][(j & 1) * 2]);
                    mma_bf16(acc[i][j], al[i], &bh[j >> 1][(j & 1) * 2]);
                }
            }
        }
        __syncthreads();
    }
#undef BF_TILE

#pragma unroll
    for (int i = 0; i < 2; i++) {
        int rbase = row0 + warpM * 32 + i * 16 + (lane >> 2);
#pragma unroll
        for (int j = 0; j < 8; j++) {
            int c = col0 + warpN * 64 + j * 8 + (lane & 3) * 2;
            float b0 = bias ? bias[c] : 0.0f;
            float b1 = bias ? bias[c + 1] : 0.0f;
            float v0 = acc[i][j][0] + b0;
            float v1 = acc[i][j][1] + b1;
            float v2 = acc[i][j][2] + b0;
            float v3 = acc[i][j][3] + b1;
            if (relu) {
                v0 = fmaxf(v0, 0.f); v1 = fmaxf(v1, 0.f);
                v2 = fmaxf(v2, 0.f); v3 = fmaxf(v3, 0.f);
            }
            if (rbase < Nr)
                *reinterpret_cast<float2*>(&Cf[(size_t)rbase * Mout + c]) =
                    make_float2(v0, v1);
            if (rbase + 8 < Nr)
                *reinterpret_cast<float2*>(
                    &Cf[(size_t)(rbase + 8) * Mout + c]) =
                    make_float2(v2, v3);
        }
    }
}

// ---------------- edge attention: raw leaky logits (edge-parallel) ----------
__global__ void attn_kernel(const float* __restrict__ edge_attr,
                            const float* __restrict__ We_l) {
    int idx = blockIdx.x * blockDim.x + threadIdx.x;
    if (idx >= N_EDGES * NHEAD) return;
    int e = idx >> 3;
    int nh = idx & 7;
    int s = g_src[e];
    int d = g_dst[e];
    const uint4* q4 =
        reinterpret_cast<const uint4*>(g_qh + d * HID + nh * HDIM);
    const uint4* k4 =
        reinterpret_cast<const uint4*>(g_kh + s * HID + nh * HDIM);
    float acc = 0.0f;
#pragma unroll
    for (int i = 0; i < 4; i++) {
        uint4 qa = q4[i];
        uint4 ka = k4[i];
        const __half2* qh = reinterpret_cast<const __half2*>(&qa);
        const __half2* kh = reinterpret_cast<const __half2*>(&ka);
#pragma unroll
        for (int j = 0; j < 4; j++) {
            float2 qf = __half22float2(qh[j]);
            float2 kf = __half22float2(kh[j]);
            acc = fmaf(qf.x, kf.x, acc);
            acc = fmaf(qf.y, kf.y, acc);
        }
    }
    float eb = edge_attr[e * 3 + 0] * We_l[nh] +
               edge_attr[e * 3 + 1] * We_l[8 + nh] +
               edge_attr[e * 3 + 2] * We_l[16 + nh];
    float a = acc * ATTN_SCALE + eb;
    a = (a > 0.0f) ? a : 0.2f * a;       // leaky_relu
    g_attn[idx] = a;
}

// ---------------- fused softmax + weighted V aggregation --------------------
// One block (256 threads, 8 warps) per destination node; warp w = head w.
// Per-node-per-head max shift (softmax shift-invariance; clip cannot bind).
__global__ __launch_bounds__(256)
void agg_fused() {
    __shared__ int s_e[CAP];
    __shared__ int s_s[CAP];
    __shared__ float s_w[CAP * NHEAD];
    __shared__ float s_m[NHEAD], s_i[NHEAD];

    int n = blockIdx.x;
    int tid = threadIdx.x;
    int wid = tid >> 5;
    int lane = tid & 31;
    int row = g_rowstart[n];
    int deg = g_rowstart[n + 1] - row;
    int dcap = min(deg, CAP);

    for (int j = tid; j < dcap; j += 256) {
        int e = g_perm[row + j];
        s_e[j] = e;
        s_s[j] = g_src[e];
    }
    __syncthreads();

    {
        float m = -3.4e38f;
        for (int j = lane; j < dcap; j += 32)
            m = fmaxf(m, g_attn[s_e[j] * NHEAD + wid]);
        for (int j = CAP + lane; j < deg; j += 32)
            m = fmaxf(m, g_attn[g_perm[row + j] * NHEAD + wid]);
#pragma unroll
        for (int o = 16; o > 0; o >>= 1)
            m = fmaxf(m, __shfl_xor_sync(0xffffffffu, m, o));
        float sum = 0.0f;
        for (int j = lane; j < dcap; j += 32) {
            float v = __expf(g_attn[s_e[j] * NHEAD + wid] - m);
            s_w[j * NHEAD + wid] = v;
            sum += v;
        }
        for (int j = CAP + lane; j < deg; j += 32)
            sum += __expf(g_attn[g_perm[row + j] * NHEAD + wid] - m);
#pragma unroll
        for (int o = 16; o > 0; o >>= 1)
            sum += __shfl_xor_sync(0xffffffffu, sum, o);
        float inv = (deg > 0) ? 1.0f / fmaxf(sum, 1e-12f) : 0.0f;
        for (int j = lane; j < dcap; j += 32)
            s_w[j * NHEAD + wid] *= inv;
        if (lane == 0) { s_m[wid] = m; s_i[wid] = inv; }
    }
    __syncthreads();

    int nh = tid >> 5;
    float acc = 0.0f;
    for (int j = 0; j < dcap; j++)
        acc += s_w[j * NHEAD + nh] * __half2float(g_vh[s_s[j] * HID + tid]);
    for (int j = CAP; j < deg; j++) {            // fallback (deg > CAP: never)
        int e = g_perm[row + j];
        float w = __expf(g_attn[e * NHEAD + nh] - s_m[nh]) * s_i[nh];
        acc += w * __half2float(g_vh[g_src[e] * HID + tid]);
    }
    g_agg_f16[n * HID + tid] = __float2half(acc);
}

// ---------------- residual + LayerNorm: h = LN(h + upd)*gamma + beta --------
__global__ void ln_kernel(const float* __restrict__ upd,
                          const float* __restrict__ gamma_l,
                          const float* __restrict__ beta_l, int last) {
    int n = blockIdx.x;
    int t = threadIdx.x;   // 256
    float x = g_h[n * HID + t] + upd[n * HID + t];
    __shared__ float s1[8], s2[8];
    float a = x, b = x * x;
#pragma unroll
    for (int o = 16; o > 0; o >>= 1) {
        a += __shfl_down_sync(0xffffffffu, a, o);
        b += __shfl_down_sync(0xffffffffu, b, o);
    }
    int warp = t >> 5, lane = t & 31;
    if (lane == 0) { s1[warp] = a; s2[warp] = b; }
    __syncthreads();
    if (warp == 0) {
        a = (lane < 8) ? s1[lane] : 0.0f;
        b = (lane < 8) ? s2[lane] : 0.0f;
#pragma unroll
        for (int o = 4; o > 0; o >>= 1) {
            a += __shfl_down_sync(0xffffffffu, a, o);
            b += __shfl_down_sync(0xffffffffu, b, o);
        }
        if (lane == 0) { s1[0] = a; s2[0] = b; }
    }
    __syncthreads();
    float mu = s1[0] * (1.0f / HID);
    float var = s2[0] * (1.0f / HID) - mu * mu;
    float r = (x - mu) * rsqrtf(var + 1e-5f) * gamma_l[t] + beta_l[t];
    g_h[n * HID + t] = r;
    g_h_f16[n * HID + t] = __float2half(r);
    if (last) {
        bf16 hi, lo;
        split_bf16(r, hi, lo);
        g_h_hi[n * HID + t] = hi;
        g_h_lo[n * HID + t] = lo;
    }
}

// ---------------- output head 2: out = hidden(N,128) @ W2(128,1) + b2 -------
__global__ void head2_kernel(const float* __restrict__ hidden,
                             const float* __restrict__ W2,
                             const float* __restrict__ b2,
                             float* __restrict__ out) {
    int gw = (blockIdx.x * blockDim.x + threadIdx.x) >> 5;
    int lane = threadIdx.x & 31;
    if (gw >= N_NODES) return;
    float acc = 0.0f;
#pragma unroll
    for (int i = 0; i < 4; i++) {
        int c = lane + i * 32;
        acc += hidden[gw * 128 + c] * W2[c];
    }
#pragma unroll
    for (int o = 16; o > 0; o >>= 1)
        acc += __shfl_down_sync(0xffffffffu, acc, o);
    if (lane == 0) out[gw] = acc + b2[0];
}

// ---------------- launch ----------------------------------------------------
extern "C" void kernel_launch(void* const* d_in, const int* in_sizes, int n_in,
                              void* d_out, int out_size) {
    const float* x         = (const float*)d_in[0];
    const float* edge_attr = (const float*)d_in[1];
    const float* W_in      = (const float*)d_in[2];
    const float* b_in      = (const float*)d_in[3];
    const float* Wq        = (const float*)d_in[4];
    const float* Wk        = (const float*)d_in[5];
    const float* Wv        = (const float*)d_in[6];
    const float* We        = (const float*)d_in[7];
    const float* Wo        = (const float*)d_in[8];
    const float* bo        = (const float*)d_in[9];
    const float* Wm        = (const float*)d_in[10];
    const float* bm        = (const float*)d_in[11];
    const float* gamma     = (const float*)d_in[12];
    const float* beta      = (const float*)d_in[13];
    const float* Wh1       = (const float*)d_in[14];
    const float* bh1       = (const float*)d_in[15];
    const float* Wh2       = (const float*)d_in[16];
    const float* bh2       = (const float*)d_in[17];
    const int*   ei_raw    = (const int*)d_in[18];

    bf16 *phhi, *phlo;
    float *pupd, *phid;
    __half *pqh, *pkh, *pvh, *phf16, *pagg16, *pao16;
    cudaGetSymbolAddress((void**)&phhi,   g_h_hi);
    cudaGetSymbolAddress((void**)&phlo,   g_h_lo);
    cudaGetSymbolAddress((void**)&pupd,   g_upd);
    cudaGetSymbolAddress((void**)&phid,   g_hid);
    cudaGetSymbolAddress((void**)&pqh,    g_qh);
    cudaGetSymbolAddress((void**)&pkh,    g_kh);
    cudaGetSymbolAddress((void**)&pvh,    g_vh);
    cudaGetSymbolAddress((void**)&phf16,  g_h_f16);
    cudaGetSymbolAddress((void**)&pagg16, g_agg_f16);
    cudaGetSymbolAddress((void**)&pao16,  g_ao_f16);

    cudaFuncSetAttribute(gemm_f16, cudaFuncAttributeMaxDynamicSharedMemorySize,
                         SMEM_F16);
    cudaFuncSetAttribute(gemm_f16b, cudaFuncAttributeMaxDynamicSharedMemorySize,
                         SMEM_F16);
    cudaFuncSetAttribute(gemm_bf16, cudaFuncAttributeMaxDynamicSharedMemorySize,
                         SMEM_BF16);

    const int NH_ELEMS = N_NODES * HID;

    // decode edge indices + build CSR (by dst)
    detect_idx<<<1, 256>>>(ei_raw);
    convert_idx<<<(N_EDGES + 255) / 256, 256>>>(ei_raw);
    zero_cnt<<<(N_NODES + 255) / 256, 256>>>();
    count_deg<<<(N_EDGES + 255) / 256, 256>>>();
    scan_rowstart<<<1, 1024>>>();
    copy_cursor<<<(N_NODES + 255) / 256, 256>>>();
    scatter_perm<<<(N_EDGES + 255) / 256, 256>>>();

    // pre-convert weights (QKV/Wo/Wm also to fp16)
    convert_w<<<(196608 + 255) / 256, 256>>>(Wq, 196608, OFF_WQ, 1);
    convert_w<<<(196608 + 255) / 256, 256>>>(Wk, 196608, OFF_WK, 1);
    convert_w<<<(196608 + 255) / 256, 256>>>(Wv, 196608, OFF_WV, 1);
    convert_w<<<(196608 + 255) / 256, 256>>>(Wo, 196608, OFF_WO, 1);
    convert_w<<<(393216 + 255) / 256, 256>>>(Wm, 393216, OFF_WM, 1);
    convert_w<<<(32768 + 255) / 256, 256>>>(Wh1, 32768, OFF_WH1, 0);

    input_proj<<<(NH_ELEMS + 255) / 256, 256>>>(x, W_in, b_in);

    int rows = (N_NODES + 127) / 128;   // 391
    dim3 gridQKV(6, rows);
    dim3 grid1(2, rows);
    dim3 gridHead(1, rows);

    for (int l = 0; l < NLAYER; l++) {
        int offQ = OFF_WQ + l * 65536;
        int offK = OFF_WK + l * 65536;
        int offV = OFF_WV + l * 65536;
        int offO = OFF_WO + l * 65536;
        int offM = OFF_WM + l * 131072;
        const float* We_l = We + l * 3 * NHEAD;
        const float* bo_l = bo + l * HID;
        const float* bm_l = bm + l * HID;
        const float* ga_l = gamma + l * HID;
        const float* be_l = beta + l * HID;

        // fused QKV: dedicated fp16 single-term kernel
        gemm_f16<<<gridQKV, 256, SMEM_F16>>>(phf16, offQ, offK, offV,
                                             pqh, pkh, pvh, N_NODES);

        // edge logits (edge-parallel), then fused softmax+aggregate
        attn_kernel<<<(N_EDGES * NHEAD + 255) / 256, 256>>>(edge_attr, We_l);
        agg_fused<<<N_NODES, 256>>>();

        // aggO = agg @ Wo + bo  -> fp16
        gemm_f16b<<<grid1, 256, SMEM_F16>>>(
            pagg16, nullptr, offO, bo_l, nullptr, pao16, N_NODES, 256, 0);
        // upd = relu(concat([h, aggO]) @ Wm + bm)  -> fp32
        gemm_f16b<<<grid1, 256, SMEM_F16>>>(
            phf16, pao16, offM, bm_l, pupd, nullptr, N_NODES, 512, 1);
        // h = LN(h + upd) * gamma + beta  (hi/lo only on last layer)
        ln_kernel<<<N_NODES, 256>>>(pupd, ga_l, be_l, l == NLAYER - 1);
    }

    // head: hidden = relu(h @ Wh1 + bh1) -> fp32 (3-term bf16 for accuracy)
    gemm_bf16<<<gridHead, 256, SMEM_BF16>>>(
        phhi, phlo, OFF_WH1, bh1, phid, N_NODES, 256, 128, 1);
    head2_kernel<<<(N_NODES * 32 + 255) / 256, 256>>>(phid, Wh2, bh2,
                                                      (float*)d_out);
}